// round 5
// baseline (speedup 1.0000x reference)
#include <cuda_runtime.h>
#include <cstdint>

// out = LeakyReLU( D^-1 * (A @ (X @ W^T)) + b ),  B=32, N=1024, F=128
// Base-ISA tensor path (mma.sync m16n8k8 tf32 + cp.async); tcgen05 unavailable
// (harness PTX target is compute_103, no 'a' suffix).
//
// k_xw  : XW = X @ W^T (Markidis 3-term tf32 ~ fp32 accuracy), output written in
//         k_main's per-thread FRAGMENT order -> k_main B loads are LDS.128.
// k_main: C = A @ XW per batch; deg = rowsum(A) fused via FADD on the idle fma
//         pipe; epilogue leaky(C/deg + bias).

#define NEG_SLOPE 0.01f

__device__ float g_xw[32u * 1024u * 128u];  // packed-fragment XW (16 MB)

// ---------------- helpers ----------------
__device__ __forceinline__ uint32_t su32(const void* p) {
    uint32_t r;
    asm("{\n\t.reg .u64 t;\n\tcvta.to.shared.u64 t, %1;\n\tcvt.u32.u64 %0, t;\n\t}"
        : "=r"(r) : "l"(p));
    return r;
}
__device__ __forceinline__ void cp16(uint32_t dst, const void* src) {
    asm volatile("cp.async.cg.shared.global [%0], [%1], 16;" :: "r"(dst), "l"(src));
}
__device__ __forceinline__ void cp_commit() {
    asm volatile("cp.async.commit_group;" ::: "memory");
}
template <int N>
__device__ __forceinline__ void cp_wait() {
    asm volatile("cp.async.wait_group %0;" :: "n"(N) : "memory");
}
__device__ __forceinline__ uint32_t tf32_rna(float x) {
    uint32_t r;
    asm("cvt.rna.tf32.f32 %0, %1;" : "=r"(r) : "f"(x));
    return r;
}
__device__ __forceinline__ void mma8(float* c, const uint32_t* a, const uint32_t* b) {
    asm volatile(
        "mma.sync.aligned.m16n8k8.row.col.f32.tf32.tf32.f32 "
        "{%0,%1,%2,%3}, {%4,%5,%6,%7}, {%8,%9}, {%0,%1,%2,%3};"
        : "+f"(c[0]), "+f"(c[1]), "+f"(c[2]), "+f"(c[3])
        : "r"(a[0]), "r"(a[1]), "r"(a[2]), "r"(a[3]), "r"(b[0]), "r"(b[1]));
}
__device__ __forceinline__ float leaky(float v) {
    return (v >= 0.0f) ? v : NEG_SLOPE * v;
}

#define AP 36   // A/X smem row pad (floats): conflict-free scalar frag LDS
#define BP 132  // W smem row pad (k_xw)

// =====================================================================
// k_xw: XW = X @ W^T.  grid=256 (m-tiles of 128), 256 threads.
// smem: Ws[128][BP] | Xs[2][128][AP]; staging reuses sm[0..16384) at the end.
// Output: packed fragment layout, per batch (131072 floats):
//   float_idx = stage*4096 + wc*2048 + k0i*512 + lane*16 + ni*2 + pair
//   where stage=m>>5, k=m&31, k0i=k>>3, pair=(k>>2)&1, lane=(o&7)*4+(k&3),
//         wc=o>>6, ni=(o>>3)&7.
// =====================================================================
#define XW_SMEM ((128 * BP + 2 * 128 * AP) * 4)

__global__ __launch_bounds__(256, 2) void k_xw(const float* __restrict__ X,
                                               const float* __restrict__ W) {
    extern __shared__ float sm[];
    float* Ws = sm;                 // 128*BP floats
    float* Xs = sm + 128 * BP;      // 2*128*AP floats
    const uint32_t ws_a = su32(Ws), xs_a = su32(Xs);

    const int tid = threadIdx.x, lane = tid & 31, wid = tid >> 5;
    const int g = lane >> 2, tig = lane & 3;
    const int wr = wid & 3, wc = wid >> 2;
    const int m0 = blockIdx.x * 128;

    // async-load whole W [128][128] -> Ws[o][f]
#pragma unroll
    for (int i = 0; i < 16; i++) {
        int idx = tid + i * 256;
        int o = idx >> 5, f4 = idx & 31;
        cp16(ws_a + (uint32_t)(o * BP + f4 * 4) * 4, W + o * 128 + f4 * 4);
    }
    cp_commit();

    const int lr = tid >> 3, lc4 = tid & 7;
    auto loadX = [&](int buf, int kt) {
#pragma unroll
        for (int i = 0; i < 4; i++) {
            int row = lr + i * 32;
            cp16(xs_a + (uint32_t)((buf * 128 + row) * AP + lc4 * 4) * 4,
                 X + (size_t)(m0 + row) * 128 + kt * 32 + lc4 * 4);
        }
        cp_commit();
    };
    loadX(0, 0);

    float acc[2][8][4];
#pragma unroll
    for (int mi = 0; mi < 2; mi++)
#pragma unroll
        for (int ni = 0; ni < 8; ni++)
#pragma unroll
            for (int q = 0; q < 4; q++) acc[mi][ni][q] = 0.0f;

    for (int kt = 0; kt < 4; kt++) {
        if (kt < 3) { loadX((kt + 1) & 1, kt + 1); cp_wait<1>(); }
        else cp_wait<0>();
        __syncthreads();
        const int buf = kt & 1;
#pragma unroll
        for (int k0 = 0; k0 < 32; k0 += 8) {
            uint32_t ah[2][4], al[2][4];
#pragma unroll
            for (int mi = 0; mi < 2; mi++) {
                int row = wr * 32 + mi * 16 + g;
#pragma unroll
                for (int q = 0; q < 4; q++) {
                    int rr = row + (q & 1) * 8, cc = k0 + tig + (q >> 1) * 4;
                    float x = Xs[(buf * 128 + rr) * AP + cc];
                    uint32_t h = tf32_rna(x);
                    ah[mi][q] = h;
                    al[mi][q] = __float_as_uint(x - __uint_as_float(h));
                }
            }
#pragma unroll
            for (int ni = 0; ni < 8; ni++) {
                int o = wc * 64 + ni * 8 + g;
                uint32_t bh[2], bl[2];
#pragma unroll
                for (int q = 0; q < 2; q++) {
                    float w = Ws[o * BP + kt * 32 + k0 + tig + q * 4];
                    uint32_t h = tf32_rna(w);
                    bh[q] = h;
                    bl[q] = __float_as_uint(w - __uint_as_float(h));
                }
#pragma unroll
                for (int mi = 0; mi < 2; mi++) {
                    mma8(acc[mi][ni], ah[mi], bh);
                    mma8(acc[mi][ni], ah[mi], bl);
                    mma8(acc[mi][ni], al[mi], bh);
                }
            }
        }
        __syncthreads();
    }

    // ---- stage accumulators into smem in packed-fragment order ----
    // C-fragment layout: q=0 ->(row,col), q=1 ->(row,col+1), q=2 ->(row+8,col),
    // q=3 ->(row+8,col+1). So row offset = q>>1, col offset = q&1.
    // m_local = wr*32 + mi*16 + (q>>1)*8 + g  -> stage_local = wr,
    //   k = m_local & 31, k0i = mi*2 + (q>>1), tig_t = g&3, pair = (g>>2)&1.
    // o = wc*64 + ni*8 + tig*2 + (q&1) -> g_t = tig*2 + (q&1).
#pragma unroll
    for (int mi = 0; mi < 2; mi++)
#pragma unroll
        for (int ni = 0; ni < 8; ni++)
#pragma unroll
            for (int q = 0; q < 4; q++) {
                int qr = q >> 1;  // row +8
                int qc = q & 1;   // col +1
                int idx = ((((wr * 2 + wc) * 4 + mi * 2 + qr) * 32) +
                           (tig * 2 + qc) * 4 + (g & 3)) * 16 +
                          ni * 2 + ((g >> 2) & 1);
                sm[idx] = acc[mi][ni][q];
            }
    __syncthreads();

    // coalesced copy of the CTA's 16384-float packed region
    const float4* s4 = (const float4*)sm;
    float4* dst = (float4*)(g_xw + (size_t)(blockIdx.x >> 3) * 131072 +
                            (size_t)(blockIdx.x & 7) * 16384);
#pragma unroll
    for (int i = 0; i < 16; i++) dst[tid + i * 256] = s4[tid + i * 256];
}

// =====================================================================
// k_main: per batch C = A[1024,1024] @ XW; deg fused as FADD; grid (8,32).
// smem bytes: As 2*128*AP*4 = 36864 | Bs 2*256*80 = 40960 | degs 512
// B stage layout: 256 blocks of 64B data at 80B stride (conflict-free LDS.128)
// =====================================================================
#define AS_BYTES (2 * 128 * AP * 4)
#define BS_BYTES (2 * 256 * 80)
#define MAIN_SMEM (AS_BYTES + BS_BYTES + 512)

__global__ __launch_bounds__(256, 2) void k_main(const float* __restrict__ A,
                                                 const float* __restrict__ bias,
                                                 float* __restrict__ out) {
    extern __shared__ float sm[];
    float* As = sm;
    char* smc = (char*)sm;
    float* degs = (float*)(smc + AS_BYTES + BS_BYTES);
    const uint32_t as_a = su32(As), bs_a = su32(smc + AS_BYTES);

    const int tid = threadIdx.x, lane = tid & 31, wid = tid >> 5;
    const int g = lane >> 2, tig = lane & 3;
    const int wr = wid & 3, wc = wid >> 2;
    const int m0 = blockIdx.x * 128, bz = blockIdx.y;
    const float* Ab = A + (size_t)bz * 1024 * 1024;
    const float* Bp = g_xw + (size_t)bz * 131072;  // packed

    const int lr = tid >> 3, lc4 = tid & 7;  // A: 128 rows x 8 f4

    auto loadT = [&](int buf, int s) {
#pragma unroll
        for (int i = 0; i < 4; i++) {
            int row = lr + i * 32;
            cp16(as_a + (uint32_t)((buf * 128 + row) * AP + lc4 * 4) * 4,
                 Ab + (size_t)(m0 + row) * 1024 + s * 32 + lc4 * 4);
        }
        // B: 1024 chunks of 16B; gmem dense, smem 64B-blocks at 80B stride
        const float* src = Bp + s * 4096;
#pragma unroll
        for (int i = 0; i < 4; i++) {
            int chunk = tid + i * 256;
            cp16(bs_a + (uint32_t)(buf * 20480 + (chunk >> 2) * 80 + (chunk & 3) * 16),
                 src + chunk * 4);
        }
        cp_commit();
    };

    float acc[2][8][4];
#pragma unroll
    for (int mi = 0; mi < 2; mi++)
#pragma unroll
        for (int ni = 0; ni < 8; ni++)
#pragma unroll
            for (int q = 0; q < 4; q++) acc[mi][ni][q] = 0.0f;
    float dg[2][2] = {{0.0f, 0.0f}, {0.0f, 0.0f}};

    loadT(0, 0);

    for (int s = 0; s < 32; s++) {
        if (s < 31) { loadT((s + 1) & 1, s + 1); cp_wait<1>(); }
        else cp_wait<0>();
        __syncthreads();
        const int buf = s & 1;
#pragma unroll
        for (int k0 = 0; k0 < 32; k0 += 8) {
            uint32_t a[2][4];
#pragma unroll
            for (int mi = 0; mi < 2; mi++) {
                int row = wr * 32 + mi * 16 + g;
#pragma unroll
                for (int q = 0; q < 4; q++) {
                    int rr = row + (q & 1) * 8, cc = k0 + tig + (q >> 1) * 4;
                    a[mi][q] = __float_as_uint(As[(buf * 128 + rr) * AP + cc]);
                }
            }
            // B fragments: 4x LDS.128, conflict-free (80B lane stride)
            const float4* bb = (const float4*)(smc + AS_BYTES + buf * 20480 +
                                               ((wc * 4 + (k0 >> 3)) * 32 + lane) * 80);
            float4 bqv[4];
#pragma unroll
            for (int j = 0; j < 4; j++) bqv[j] = bb[j];

#pragma unroll
            for (int ni = 0; ni < 8; ni++) {
                float4 qv = bqv[ni >> 1];
                float b0f = (ni & 1) ? qv.z : qv.x;
                float b1f = (ni & 1) ? qv.w : qv.y;
                uint32_t b[2] = {__float_as_uint(b0f), __float_as_uint(b1f)};
                mma8(acc[0][ni], a[0], b);
                mma8(acc[1][ni], a[1], b);
            }
            if (wc == 0) {  // degree on the idle fma pipe
#pragma unroll
                for (int mi = 0; mi < 2; mi++) {
                    dg[mi][0] += __uint_as_float(a[mi][0]) + __uint_as_float(a[mi][2]);
                    dg[mi][1] += __uint_as_float(a[mi][1]) + __uint_as_float(a[mi][3]);
                }
            }
        }
        __syncthreads();
    }

    if (wc == 0) {  // reduce deg over the tig quad (lane bits 0-1)
#pragma unroll
        for (int mi = 0; mi < 2; mi++)
#pragma unroll
            for (int r = 0; r < 2; r++) {
                float v = dg[mi][r];
                v += __shfl_xor_sync(0xffffffffu, v, 1);
                v += __shfl_xor_sync(0xffffffffu, v, 2);
                if (tig == 0) degs[wr * 32 + mi * 16 + r * 8 + g] = v;
            }
    }
    __syncthreads();

    float inv[2][2];
#pragma unroll
    for (int mi = 0; mi < 2; mi++) {
        inv[mi][0] = 1.0f / degs[wr * 32 + mi * 16 + g];
        inv[mi][1] = 1.0f / degs[wr * 32 + mi * 16 + g + 8];
    }

#pragma unroll
    for (int ni = 0; ni < 8; ni++) {
        int col = wc * 64 + ni * 8 + tig * 2;
        float2 bv = *(const float2*)(bias + col);
#pragma unroll
        for (int mi = 0; mi < 2; mi++) {
            int row = m0 + wr * 32 + mi * 16 + g;
            float2 v0, v1;
            v0.x = leaky(fmaf(acc[mi][ni][0], inv[mi][0], bv.x));
            v0.y = leaky(fmaf(acc[mi][ni][1], inv[mi][0], bv.y));
            v1.x = leaky(fmaf(acc[mi][ni][2], inv[mi][1], bv.x));
            v1.y = leaky(fmaf(acc[mi][ni][3], inv[mi][1], bv.y));
            *(float2*)(out + ((size_t)bz * 1024 + row) * 128 + col) = v0;
            *(float2*)(out + ((size_t)bz * 1024 + row + 8) * 128 + col) = v1;
        }
    }
}

// ---------------- host ----------------
extern "C" void kernel_launch(void* const* d_in, const int* in_sizes, int n_in,
                              void* d_out, int out_size) {
    const float* X    = (const float*)d_in[0];  // [32,1024,128]
    const float* adj  = (const float*)d_in[1];  // [32,1024,1024]
    const float* W    = (const float*)d_in[2];  // [128,128]
    const float* bias = (const float*)d_in[3];  // [128]
    float* out = (float*)d_out;                 // [32,1024,128]

    static int inited = 0;
    if (!inited) {
        cudaFuncSetAttribute(k_xw, cudaFuncAttributeMaxDynamicSharedMemorySize, XW_SMEM);
        cudaFuncSetAttribute(k_main, cudaFuncAttributeMaxDynamicSharedMemorySize, MAIN_SMEM);
        inited = 1;
    }

    k_xw<<<256, 256, XW_SMEM>>>(X, W);
    k_main<<<dim3(8, 32), 256, MAIN_SMEM>>>(adj, bias, out);
}